// round 3
// baseline (speedup 1.0000x reference)
#include <cuda_runtime.h>
#include <math.h>

#define BB 32
#define CC 512
#define LL 1024
#define NTOK (BB*LL)          /* 32768 tokens */
#define Q_EPS 1e-5f
#define BN_EPS 1e-5f
#define NSTATB 256            /* stats stage-1 blocks */

/* ---------------- scratch (device globals; no allocations allowed) -------- */
__device__ float       g_conv[NTOK*CC];      /* conv+bias output, [tok][c] (64MB) */
__device__ signed char g_qx  [NTOK*CC];      /* quantized activations (16MB) */
__device__ signed char g_wq  [CC*CC];        /* ternary weights */
__device__ float       g_sxinv[NTOK];        /* per-token 1/scale_x */
__device__ float       g_wscale;             /* scale_w */
__device__ float       g_winv;               /* 1/scale_w */
__device__ float       g_ps1[NSTATB*CC];     /* partial sums  */
__device__ float       g_ps2[NSTATB*CC];     /* partial sumsq */
__device__ float       g_mean[CC];
__device__ float       g_invstd[CC];

__device__ __forceinline__ float gelu_exact(float v) {
    return 0.5f * v * (1.0f + erff(v * 0.70710678118654752440f));
}

/* ---------------- K0: weight absmean -> scales ---------------------------- */
__global__ void k_wstats(const float* __restrict__ w) {
    __shared__ float sm[512];
    float s = 0.0f;
    for (int i = threadIdx.x; i < CC*CC; i += 512) s += fabsf(w[i]);
    sm[threadIdx.x] = s;
    __syncthreads();
    for (int off = 256; off; off >>= 1) {
        if (threadIdx.x < off) sm[threadIdx.x] += sm[threadIdx.x + off];
        __syncthreads();
    }
    if (threadIdx.x == 0) {
        float m = fmaxf(sm[0] / (float)(CC*CC), Q_EPS);
        g_winv   = m;          /* 1/scale */
        g_wscale = 1.0f / m;   /* scale   */
    }
}

/* ---------------- K1: ternary weight quant -------------------------------- */
__global__ void k_wquant(const float* __restrict__ w) {
    int i = blockIdx.x * 512 + threadIdx.x;
    float q = rintf(w[i] * g_wscale);
    q = fminf(fmaxf(q, -1.0f), 1.0f);
    g_wq[i] = (signed char)q;
}

/* ---------------- K2: conv1d(k=3,pad=1) + bias, fp32 ---------------------- */
/* block: 128 l x 128 o for one batch; 256 threads, 8x8 micro-tile; IC chunks
   of 8; register-prefetch double buffering of the staged tiles. */
#define ICC 8
#define XS_STRIDE 132   /* >=130, multiple of 4 for float4 alignment */
#define WS_STRIDE 136   /* >=128, multiple of 4 */
#define NXR 5           /* ceil(8*130 / 256) staged x elems per thread */
#define NWR 12          /* 128*24 / 256   staged w elems per thread */

__global__ __launch_bounds__(256, 2) void k_conv(const float* __restrict__ x,
                                                 const float* __restrict__ w,
                                                 const float* __restrict__ cb) {
    __shared__ float xs[ICC][XS_STRIDE];     /* [ic][l-1 .. l+128] (130 used) */
    __shared__ float ws[3][ICC][WS_STRIDE];  /* [k][ic][o] (128 used) */
    const int t     = threadIdx.x;
    const int lbase = blockIdx.x * 128;
    const int obase = blockIdx.y * 128;
    const int b     = blockIdx.z;
    const int l0 = (t & 15) * 8;   /* token offset within tile */
    const int o0 = (t >> 4) * 8;   /* out-channel offset within tile */
    float acc[8][8] = {};
    const float* xb = x + (size_t)b * (CC*LL);

    float xr[NXR], wr[NWR];

#define LOAD_CHUNK(IC0) do {                                                  \
        _Pragma("unroll")                                                     \
        for (int j = 0; j < NXR; j++) {                                       \
            int idx = t + j*256; float v = 0.0f;                              \
            if (idx < ICC*130) {                                              \
                int ic = idx / 130, ls = idx - ic*130, gl = lbase - 1 + ls;   \
                if (gl >= 0 && gl < LL) v = xb[((IC0) + ic) * LL + gl];       \
            }                                                                 \
            xr[j] = v;                                                        \
        }                                                                     \
        _Pragma("unroll")                                                     \
        for (int j = 0; j < NWR; j++) {                                       \
            int idx = t + j*256;                                              \
            int o = idx / 24, f = idx - o*24, ic = f / 3, k = f - ic*3;       \
            wr[j] = w[(obase + o) * (CC*3) + ((IC0) + ic) * 3 + k];           \
        }                                                                     \
    } while (0)

#define STORE_CHUNK() do {                                                    \
        _Pragma("unroll")                                                     \
        for (int j = 0; j < NXR; j++) {                                       \
            int idx = t + j*256;                                              \
            if (idx < ICC*130) {                                              \
                int ic = idx / 130, ls = idx - ic*130;                        \
                xs[ic][ls] = xr[j];                                           \
            }                                                                 \
        }                                                                     \
        _Pragma("unroll")                                                     \
        for (int j = 0; j < NWR; j++) {                                       \
            int idx = t + j*256;                                              \
            int o = idx / 24, f = idx - o*24, ic = f / 3, k = f - ic*3;       \
            ws[k][ic][o] = wr[j];                                             \
        }                                                                     \
    } while (0)

    LOAD_CHUNK(0);
    for (int ic0 = 0; ic0 < CC; ic0 += ICC) {
        STORE_CHUNK();
        __syncthreads();
        if (ic0 + ICC < CC) LOAD_CHUNK(ic0 + ICC);   /* overlap with compute */

        #pragma unroll
        for (int ic = 0; ic < ICC; ic++) {
            float4 xa = *(const float4*)&xs[ic][l0];
            float4 xm = *(const float4*)&xs[ic][l0 + 4];
            float4 xc = *(const float4*)&xs[ic][l0 + 8];
            float xf[12] = {xa.x, xa.y, xa.z, xa.w,
                            xm.x, xm.y, xm.z, xm.w,
                            xc.x, xc.y, xc.z, xc.w};
            #pragma unroll
            for (int k = 0; k < 3; k++) {
                float4 w0 = *(const float4*)&ws[k][ic][o0];
                float4 w1 = *(const float4*)&ws[k][ic][o0 + 4];
                float wv[8] = {w0.x, w0.y, w0.z, w0.w, w1.x, w1.y, w1.z, w1.w};
                #pragma unroll
                for (int j = 0; j < 8; j++) {
                    float xv = xf[j + k];
                    #pragma unroll
                    for (int i = 0; i < 8; i++)
                        acc[j][i] += xv * wv[i];
                }
            }
        }
        __syncthreads();
    }

    float4 b0 = *(const float4*)&cb[obase + o0];
    float4 b1 = *(const float4*)&cb[obase + o0 + 4];
    float bias[8] = {b0.x, b0.y, b0.z, b0.w, b1.x, b1.y, b1.z, b1.w};
    #pragma unroll
    for (int j = 0; j < 8; j++) {
        int tok = b * LL + lbase + l0 + j;
        float* row = &g_conv[(size_t)tok * CC + obase + o0];
        float4 v0, v1;
        v0.x = acc[j][0] + bias[0];  v0.y = acc[j][1] + bias[1];
        v0.z = acc[j][2] + bias[2];  v0.w = acc[j][3] + bias[3];
        v1.x = acc[j][4] + bias[4];  v1.y = acc[j][5] + bias[5];
        v1.z = acc[j][6] + bias[6];  v1.w = acc[j][7] + bias[7];
        *(float4*)&row[0] = v0;
        *(float4*)&row[4] = v1;
    }
}

/* ---------------- K3/K4: deterministic BN batch stats ---------------------- */
__global__ void k_stats1() {
    int g = blockIdx.x;            /* 256 blocks, 128 tokens each */
    int t = threadIdx.x;           /* 256 threads: channels t, t+256 */
    int tok0 = g * 128;
    float s1a = 0, s2a = 0, s1b = 0, s2b = 0;
    for (int i = 0; i < 128; i++) {
        const float* row = &g_conv[(size_t)(tok0 + i) * CC];
        float va = row[t];
        float vb = row[t + 256];
        s1a += va; s2a += va * va;
        s1b += vb; s2b += vb * vb;
    }
    g_ps1[g*CC + t] = s1a;  g_ps1[g*CC + t + 256] = s1b;
    g_ps2[g*CC + t] = s2a;  g_ps2[g*CC + t + 256] = s2b;
}

__global__ void k_stats2() {
    int c = threadIdx.x;           /* 512 threads */
    float s1 = 0, s2 = 0;
    for (int g = 0; g < NSTATB; g++) {
        s1 += g_ps1[g*CC + c];
        s2 += g_ps2[g*CC + c];
    }
    float mean = s1 * (1.0f / (float)NTOK);
    float var  = s2 * (1.0f / (float)NTOK) - mean * mean;
    g_mean[c]   = mean;
    g_invstd[c] = 1.0f / sqrtf(var + BN_EPS);
}

/* ---------------- K5: BN -> gelu -> per-token int8 quant ------------------- */
/* one block per token, 128 threads x 4 channels */
__global__ __launch_bounds__(128) void k_quant(const float* __restrict__ gamma,
                                               const float* __restrict__ beta) {
    int tok = blockIdx.x;
    int t   = threadIdx.x;
    int c   = t * 4;
    float4 v  = *(const float4*)&g_conv[(size_t)tok * CC + c];
    float4 mn = *(const float4*)&g_mean[c];
    float4 is = *(const float4*)&g_invstd[c];
    float4 ga = *(const float4*)&gamma[c];
    float4 be = *(const float4*)&beta[c];
    float gv[4];
    gv[0] = gelu_exact((v.x - mn.x) * is.x * ga.x + be.x);
    gv[1] = gelu_exact((v.y - mn.y) * is.y * ga.y + be.y);
    gv[2] = gelu_exact((v.z - mn.z) * is.z * ga.z + be.z);
    gv[3] = gelu_exact((v.w - mn.w) * is.w * ga.w + be.w);
    float m = fmaxf(fmaxf(fabsf(gv[0]), fabsf(gv[1])),
                    fmaxf(fabsf(gv[2]), fabsf(gv[3])));
    #pragma unroll
    for (int off = 16; off; off >>= 1)
        m = fmaxf(m, __shfl_xor_sync(0xffffffffu, m, off));
    __shared__ float sm[4];
    if ((t & 31) == 0) sm[t >> 5] = m;
    __syncthreads();
    m = fmaxf(fmaxf(sm[0], sm[1]), fmaxf(sm[2], sm[3]));
    float scale = 127.0f / fmaxf(m, Q_EPS);
    char4 q;
    q.x = (signed char)fminf(fmaxf(rintf(gv[0] * scale), -128.0f), 127.0f);
    q.y = (signed char)fminf(fmaxf(rintf(gv[1] * scale), -128.0f), 127.0f);
    q.z = (signed char)fminf(fmaxf(rintf(gv[2] * scale), -128.0f), 127.0f);
    q.w = (signed char)fminf(fmaxf(rintf(gv[3] * scale), -128.0f), 127.0f);
    *(char4*)&g_qx[(size_t)tok * CC + c] = q;
    if (t == 0) g_sxinv[tok] = 1.0f / scale;
}

/* ---------------- K6: int8 DP4A matmul + dequant + gelu + residual --------- */
/* block: 64 tokens x 64 out-channels; 256 threads, 4x4 micro-tile.
   tokens ride t&15 so each thread stores float4 of 4 consecutive l -> coalesced */
__global__ __launch_bounds__(256) void k_mm(const float* __restrict__ xin,
                                            float* __restrict__ out) {
    __shared__ int sA[64][65];   /* [tok][word] */
    __shared__ int sB[64][65];   /* [o][word]   */
    const int t = threadIdx.x;
    const int tokbase = blockIdx.x * 64;
    const int obase   = blockIdx.y * 64;
    const int y0 = (t & 15) * 4;   /* token  */
    const int o0 = (t >> 4) * 4;   /* out ch */
    int acc[4][4] = {};            /* [tok j][o i] */
    const int* qxw = (const int*)g_qx;
    const int* wqw = (const int*)g_wq;

    for (int kc = 0; kc < 2; kc++) {
        for (int idx = t; idx < 64*64; idx += 256) {
            int r = idx >> 6, col = idx & 63;
            sA[r][col] = qxw[(size_t)(tokbase + r) * 128 + kc * 64 + col];
            sB[r][col] = wqw[(size_t)(obase  + r) * 128 + kc * 64 + col];
        }
        __syncthreads();
        #pragma unroll 16
        for (int wd = 0; wd < 64; wd++) {
            int a[4], bw[4];
            #pragma unroll
            for (int j = 0; j < 4; j++) a[j]  = sA[y0 + j][wd];
            #pragma unroll
            for (int i = 0; i < 4; i++) bw[i] = sB[o0 + i][wd];
            #pragma unroll
            for (int j = 0; j < 4; j++)
                #pragma unroll
                for (int i = 0; i < 4; i++)
                    acc[j][i] = __dp4a(a[j], bw[i], acc[j][i]);
        }
        __syncthreads();
    }

    float winv = g_winv;
    float f[4];
    #pragma unroll
    for (int j = 0; j < 4; j++) f[j] = g_sxinv[tokbase + y0 + j] * winv;
    int b_ = tokbase >> 10;                    /* tile never crosses batch (64 | 1024) */
    int l0 = (tokbase & 1023) + y0;
    #pragma unroll
    for (int i = 0; i < 4; i++) {
        size_t gidx = (size_t)(b_ * CC + (obase + o0 + i)) * LL + l0;
        float4 r = *(const float4*)&xin[gidx];
        float4 v;
        v.x = gelu_exact((float)acc[0][i] * f[0]) + r.x;
        v.y = gelu_exact((float)acc[1][i] * f[1]) + r.y;
        v.z = gelu_exact((float)acc[2][i] * f[2]) + r.z;
        v.w = gelu_exact((float)acc[3][i] * f[3]) + r.w;
        *(float4*)&out[gidx] = v;
    }
}

/* ---------------- launch ---------------------------------------------------- */
extern "C" void kernel_launch(void* const* d_in, const int* in_sizes, int n_in,
                              void* d_out, int out_size) {
    (void)in_sizes; (void)n_in; (void)out_size;
    const float* x      = (const float*)d_in[0];
    const float* conv_w = (const float*)d_in[1];
    const float* conv_b = (const float*)d_in[2];
    const float* gamma  = (const float*)d_in[3];
    const float* beta   = (const float*)d_in[4];
    const float* proj_w = (const float*)d_in[5];
    float* out = (float*)d_out;

    k_wstats<<<1, 512>>>(proj_w);
    k_wquant<<<512, 512>>>(proj_w);
    k_conv<<<dim3(LL/128, CC/128, BB), 256>>>(x, conv_w, conv_b);
    k_stats1<<<NSTATB, 256>>>();
    k_stats2<<<1, 512>>>();
    k_quant<<<NTOK, 128>>>(gamma, beta);
    k_mm<<<dim3(NTOK/64, CC/64), 256>>>(x, out);
}

// round 11
// speedup vs baseline: 1.7119x; 1.7119x over previous
#include <cuda_runtime.h>
#include <cuda_bf16.h>
#include <math.h>
#include <stdint.h>

#define BB 32
#define CC 512
#define LL 1024
#define NTOK (BB*LL)          /* 32768 tokens */
#define Q_EPS 1e-5f
#define BN_EPS 1e-5f
#define NSTATB 256            /* stats stage-1 blocks */

/* ---------------- scratch (device globals; no allocations allowed) -------- */
__device__ float          g_conv[NTOK*CC];     /* conv+bias output, [tok][c] (64MB) */
__device__ signed char    g_qx  [NTOK*CC];     /* quantized activations (16MB) */
__device__ signed char    g_wq  [CC*CC];       /* ternary weights */
__device__ float          g_sxinv[NTOK];       /* per-token 1/scale_x */
__device__ float          g_wscale;            /* scale_w */
__device__ float          g_winv;              /* 1/scale_w */
__device__ float          g_ps1[NSTATB*CC];
__device__ float          g_ps2[NSTATB*CC];
__device__ float          g_mean[CC];
__device__ float          g_invstd[CC];
/* bf16-split operands for mma conv */
__device__ __nv_bfloat16  g_whi_t[CC*CC*3];    /* [o][k*512+ic] hi  (1.5MB) */
__device__ __nv_bfloat16  g_wlo_t[CC*CC*3];    /* [o][k*512+ic] lo  */
__device__ __nv_bfloat16  g_xhi_t[NTOK*CC];    /* [b][l][ic] hi (32MB) */
__device__ __nv_bfloat16  g_xlo_t[NTOK*CC];    /* [b][l][ic] lo (32MB) */

__device__ __forceinline__ float gelu_exact(float v) {
    return 0.5f * v * (1.0f + erff(v * 0.70710678118654752440f));
}

/* mma.sync m16n8k16 row.col f32.bf16.bf16.f32 (sm_80+ baseline feature) */
__device__ __forceinline__ void mma16816(float* c, const uint32_t* a,
                                         const uint32_t* b) {
    asm volatile(
        "mma.sync.aligned.m16n8k16.row.col.f32.bf16.bf16.f32 "
        "{%0,%1,%2,%3}, {%4,%5,%6,%7}, {%8,%9}, {%0,%1,%2,%3};"
        : "+f"(c[0]), "+f"(c[1]), "+f"(c[2]), "+f"(c[3])
        : "r"(a[0]), "r"(a[1]), "r"(a[2]), "r"(a[3]), "r"(b[0]), "r"(b[1]));
}

/* ---------------- K0: weight absmean -> scales ---------------------------- */
__global__ void k_wstats(const float* __restrict__ w) {
    __shared__ float sm[512];
    float s = 0.0f;
    for (int i = threadIdx.x; i < CC*CC; i += 512) s += fabsf(w[i]);
    sm[threadIdx.x] = s;
    __syncthreads();
    for (int off = 256; off; off >>= 1) {
        if (threadIdx.x < off) sm[threadIdx.x] += sm[threadIdx.x + off];
        __syncthreads();
    }
    if (threadIdx.x == 0) {
        float m = fmaxf(sm[0] / (float)(CC*CC), Q_EPS);
        g_winv   = m;
        g_wscale = 1.0f / m;
    }
}

/* ---------------- K1: ternary weight quant -------------------------------- */
__global__ void k_wquant(const float* __restrict__ w) {
    int i = blockIdx.x * 512 + threadIdx.x;
    float q = rintf(w[i] * g_wscale);
    q = fminf(fmaxf(q, -1.0f), 1.0f);
    g_wq[i] = (signed char)q;
}

/* ---------------- K2a: conv-weight bf16 split, [o][ic][k] -> [o][k*512+ic] - */
__global__ void k_wsplit(const float* __restrict__ w) {
    int idx = blockIdx.x * 256 + threadIdx.x;     /* 512*1536 */
    int o = idx / 1536, r = idx - o * 1536;
    int k = r >> 9, ic = r & 511;
    float v = w[o * 1536 + ic * 3 + k];
    __nv_bfloat16 h = __float2bfloat16(v);
    g_whi_t[idx] = h;
    g_wlo_t[idx] = __float2bfloat16(v - __bfloat162float(h));
}

/* ---------------- K2b: x transpose+split, [b][ic][l] -> [b][l][ic] --------- */
__global__ __launch_bounds__(256) void k_xsplit(const float* __restrict__ x) {
    __shared__ float tile[64][33];
    int b = blockIdx.z, ic0 = blockIdx.y * 64, l0 = blockIdx.x * 32;
    int tx = threadIdx.x, ty = threadIdx.y;
    const float* xb = x + ((size_t)b * CC + ic0) * LL + l0;
    for (int i = ty; i < 64; i += 8)
        tile[i][tx] = xb[(size_t)i * LL + tx];
    __syncthreads();
    for (int j = ty; j < 32; j += 8) {
        float v0 = tile[tx*2][j], v1 = tile[tx*2+1][j];
        __nv_bfloat16 h0 = __float2bfloat16(v0), h1 = __float2bfloat16(v1);
        __nv_bfloat162 hv, lv;
        hv.x = h0; hv.y = h1;
        lv.x = __float2bfloat16(v0 - __bfloat162float(h0));
        lv.y = __float2bfloat16(v1 - __bfloat162float(h1));
        size_t base = ((size_t)b * LL + l0 + j) * CC + ic0 + tx*2;
        *(__nv_bfloat162*)&g_xhi_t[base] = hv;
        *(__nv_bfloat162*)&g_xlo_t[base] = lv;
    }
}

/* ---------------- K2c: conv via mma.sync bf16 split-GEMM ------------------- */
/* CTA: 128 tok x 128 o; 8 warps, each 32 tok x 64 o.
   K = 1536 in 48 chunks of 32 (3 k-shifts x 16 ic-chunks).
   smem rows padded to 40 bf16 (80B): frag LDS and staging conflict-free. */
#define SSTR 40
__global__ __launch_bounds__(256) void k_convmma(const float* __restrict__ cb) {
    __shared__ __nv_bfloat16 sAhi[128*SSTR], sAlo[128*SSTR];
    __shared__ __nv_bfloat16 sBhi[128*SSTR], sBlo[128*SSTR];
    const int t   = threadIdx.x;
    const int wid = t >> 5, lane = t & 31;
    const int g = lane >> 2, q = lane & 3;     /* mma group / quad */
    const int warp_m = wid & 3;                /* token sub-tile (32 each) */
    const int warp_n = wid >> 2;               /* o sub-tile (64 each)    */
    const int tile  = blockIdx.x;              /* token tile, 0..255 */
    const int obase = blockIdx.y * 128;        /* o tile, 0..3 */
    const int bb  = (tile * 128) >> 10;
    const int T0l = (tile * 128) & 1023;

    float acc[2][8][4];
    #pragma unroll
    for (int mt = 0; mt < 2; mt++)
        #pragma unroll
        for (int nt = 0; nt < 8; nt++)
            #pragma unroll
            for (int r = 0; r < 4; r++) acc[mt][nt][r] = 0.0f;

    const int srow = t >> 2, sseg = t & 3;     /* staging: 4 thr x 16B per row */

    for (int k = 0; k < 3; k++)
    for (int ic0 = 0; ic0 < 512; ic0 += 32) {
        /* ---- stage A (tokens, shifted) hi/lo: 128 rows x 32 bf16 ---- */
        #pragma unroll
        for (int it = 0; it < 2; it++) {
            int row = srow + it * 64;
            int lp  = T0l + row + k - 1;
            uint4 vh = make_uint4(0,0,0,0), vl = vh;
            if (lp >= 0 && lp < LL) {
                size_t sidx = ((size_t)(bb * LL + lp)) * CC + ic0 + sseg * 8;
                vh = *(const uint4*)&g_xhi_t[sidx];
                vl = *(const uint4*)&g_xlo_t[sidx];
            }
            *(uint4*)&sAhi[row*SSTR + sseg*8] = vh;
            *(uint4*)&sAlo[row*SSTR + sseg*8] = vl;
        }
        /* ---- stage B (weights) hi/lo: 128 rows x 32 bf16 ---- */
        #pragma unroll
        for (int it = 0; it < 2; it++) {
            int row = srow + it * 64;
            size_t sidx = ((size_t)(obase + row)) * 1536 + k * 512 + ic0 + sseg * 8;
            *(uint4*)&sBhi[row*SSTR + sseg*8] = *(const uint4*)&g_whi_t[sidx];
            *(uint4*)&sBlo[row*SSTR + sseg*8] = *(const uint4*)&g_wlo_t[sidx];
        }
        __syncthreads();

        #pragma unroll
        for (int ks = 0; ks < 2; ks++) {
            /* A fragments: rows = warp_m*32 + mt*16 + {g, g+8}, k-cols ks*16.. */
            uint32_t ahi[2][4], alo[2][4];
            #pragma unroll
            for (int mt = 0; mt < 2; mt++) {
                int base = (warp_m*32 + mt*16 + g) * SSTR + ks*16 + 2*q;
                ahi[mt][0] = *(const uint32_t*)&sAhi[base];
                ahi[mt][1] = *(const uint32_t*)&sAhi[base + 8*SSTR];
                ahi[mt][2] = *(const uint32_t*)&sAhi[base + 8];
                ahi[mt][3] = *(const uint32_t*)&sAhi[base + 8*SSTR + 8];
                alo[mt][0] = *(const uint32_t*)&sAlo[base];
                alo[mt][1] = *(const uint32_t*)&sAlo[base + 8*SSTR];
                alo[mt][2] = *(const uint32_t*)&sAlo[base + 8];
                alo[mt][3] = *(const uint32_t*)&sAlo[base + 8*SSTR + 8];
            }
            #pragma unroll
            for (int nt = 0; nt < 8; nt++) {
                int nb = (warp_n*64 + nt*8 + g) * SSTR + ks*16 + 2*q;
                uint32_t bhi[2], blo[2];
                bhi[0] = *(const uint32_t*)&sBhi[nb];
                bhi[1] = *(const uint32_t*)&sBhi[nb + 8];
                blo[0] = *(const uint32_t*)&sBlo[nb];
                blo[1] = *(const uint32_t*)&sBlo[nb + 8];
                #pragma unroll
                for (int mt = 0; mt < 2; mt++) {
                    mma16816(acc[mt][nt], ahi[mt], bhi);
                    mma16816(acc[mt][nt], ahi[mt], blo);
                    mma16816(acc[mt][nt], alo[mt], bhi);
                }
            }
        }
        __syncthreads();
    }

    /* epilogue: c0,c1 -> row g, cols 2q,2q+1 ; c2,c3 -> row g+8 */
    #pragma unroll
    for (int mt = 0; mt < 2; mt++) {
        int tok0 = tile*128 + warp_m*32 + mt*16 + g;
        #pragma unroll
        for (int nt = 0; nt < 8; nt++) {
            int oc = obase + warp_n*64 + nt*8 + 2*q;
            float2 bias = *(const float2*)&cb[oc];
            float2 v0, v1;
            v0.x = acc[mt][nt][0] + bias.x;  v0.y = acc[mt][nt][1] + bias.y;
            v1.x = acc[mt][nt][2] + bias.x;  v1.y = acc[mt][nt][3] + bias.y;
            *(float2*)&g_conv[(size_t)tok0 * CC + oc]       = v0;
            *(float2*)&g_conv[(size_t)(tok0 + 8) * CC + oc] = v1;
        }
    }
}

/* ---------------- K3/K4: deterministic BN batch stats ---------------------- */
__global__ void k_stats1() {
    int g = blockIdx.x;
    int t = threadIdx.x;
    int tok0 = g * 128;
    float s1a = 0, s2a = 0, s1b = 0, s2b = 0;
    for (int i = 0; i < 128; i++) {
        const float* row = &g_conv[(size_t)(tok0 + i) * CC];
        float va = row[t];
        float vb = row[t + 256];
        s1a += va; s2a += va * va;
        s1b += vb; s2b += vb * vb;
    }
    g_ps1[g*CC + t] = s1a;  g_ps1[g*CC + t + 256] = s1b;
    g_ps2[g*CC + t] = s2a;  g_ps2[g*CC + t + 256] = s2b;
}

__global__ void k_stats2() {
    int c = threadIdx.x;
    float s1 = 0, s2 = 0;
    for (int g = 0; g < NSTATB; g++) {
        s1 += g_ps1[g*CC + c];
        s2 += g_ps2[g*CC + c];
    }
    float mean = s1 * (1.0f / (float)NTOK);
    float var  = s2 * (1.0f / (float)NTOK) - mean * mean;
    g_mean[c]   = mean;
    g_invstd[c] = 1.0f / sqrtf(var + BN_EPS);
}

/* ---------------- K5: BN -> gelu -> per-token int8 quant ------------------- */
__global__ __launch_bounds__(128) void k_quant(const float* __restrict__ gamma,
                                               const float* __restrict__ beta) {
    int tok = blockIdx.x;
    int t   = threadIdx.x;
    int c   = t * 4;
    float4 v  = *(const float4*)&g_conv[(size_t)tok * CC + c];
    float4 mn = *(const float4*)&g_mean[c];
    float4 is = *(const float4*)&g_invstd[c];
    float4 ga = *(const float4*)&gamma[c];
    float4 be = *(const float4*)&beta[c];
    float gv[4];
    gv[0] = gelu_exact((v.x - mn.x) * is.x * ga.x + be.x);
    gv[1] = gelu_exact((v.y - mn.y) * is.y * ga.y + be.y);
    gv[2] = gelu_exact((v.z - mn.z) * is.z * ga.z + be.z);
    gv[3] = gelu_exact((v.w - mn.w) * is.w * ga.w + be.w);
    float m = fmaxf(fmaxf(fabsf(gv[0]), fabsf(gv[1])),
                    fmaxf(fabsf(gv[2]), fabsf(gv[3])));
    #pragma unroll
    for (int off = 16; off; off >>= 1)
        m = fmaxf(m, __shfl_xor_sync(0xffffffffu, m, off));
    __shared__ float sm[4];
    if ((t & 31) == 0) sm[t >> 5] = m;
    __syncthreads();
    m = fmaxf(fmaxf(sm[0], sm[1]), fmaxf(sm[2], sm[3]));
    float scale = 127.0f / fmaxf(m, Q_EPS);
    char4 qv;
    qv.x = (signed char)fminf(fmaxf(rintf(gv[0] * scale), -128.0f), 127.0f);
    qv.y = (signed char)fminf(fmaxf(rintf(gv[1] * scale), -128.0f), 127.0f);
    qv.z = (signed char)fminf(fmaxf(rintf(gv[2] * scale), -128.0f), 127.0f);
    qv.w = (signed char)fminf(fmaxf(rintf(gv[3] * scale), -128.0f), 127.0f);
    *(char4*)&g_qx[(size_t)tok * CC + c] = qv;
    if (t == 0) g_sxinv[tok] = 1.0f / scale;
}

/* ---------------- K6: int8 DP4A matmul + dequant + gelu + residual --------- */
__global__ __launch_bounds__(256) void k_mm(const float* __restrict__ xin,
                                            float* __restrict__ out) {
    __shared__ int sA[64][65];
    __shared__ int sB[64][65];
    const int t = threadIdx.x;
    const int tokbase = blockIdx.x * 64;
    const int obase   = blockIdx.y * 64;
    const int y0 = (t & 15) * 4;
    const int o0 = (t >> 4) * 4;
    int acc[4][4] = {};
    const int* qxw = (const int*)g_qx;
    const int* wqw = (const int*)g_wq;

    for (int kc = 0; kc < 2; kc++) {
        for (int idx = t; idx < 64*64; idx += 256) {
            int r = idx >> 6, col = idx & 63;
            sA[r][col] = qxw[(size_t)(tokbase + r) * 128 + kc * 64 + col];
            sB[r][col] = wqw[(size_t)(obase  + r) * 128 + kc * 64 + col];
        }
        __syncthreads();
        #pragma unroll 16
        for (int wd = 0; wd < 64; wd++) {
            int a[4], bw[4];
            #pragma unroll
            for (int j = 0; j < 4; j++) a[j]  = sA[y0 + j][wd];
            #pragma unroll
            for (int i = 0; i < 4; i++) bw[i] = sB[o0 + i][wd];
            #pragma unroll
            for (int j = 0; j < 4; j++)
                #pragma unroll
                for (int i = 0; i < 4; i++)
                    acc[j][i] = __dp4a(a[j], bw[i], acc[j][i]);
        }
        __syncthreads();
    }

    float winv = g_winv;
    float f[4];
    #pragma unroll
    for (int j = 0; j < 4; j++) f[j] = g_sxinv[tokbase + y0 + j] * winv;
    int b_ = tokbase >> 10;
    int l0 = (tokbase & 1023) + y0;
    #pragma unroll
    for (int i = 0; i < 4; i++) {
        size_t gidx = (size_t)(b_ * CC + (obase + o0 + i)) * LL + l0;
        float4 r = *(const float4*)&xin[gidx];
        float4 v;
        v.x = gelu_exact((float)acc[0][i] * f[0]) + r.x;
        v.y = gelu_exact((float)acc[1][i] * f[1]) + r.y;
        v.z = gelu_exact((float)acc[2][i] * f[2]) + r.z;
        v.w = gelu_exact((float)acc[3][i] * f[3]) + r.w;
        *(float4*)&out[gidx] = v;
    }
}

/* ---------------- launch ---------------------------------------------------- */
extern "C" void kernel_launch(void* const* d_in, const int* in_sizes, int n_in,
                              void* d_out, int out_size) {
    (void)in_sizes; (void)n_in; (void)out_size;
    const float* x      = (const float*)d_in[0];
    const float* conv_w = (const float*)d_in[1];
    const float* conv_b = (const float*)d_in[2];
    const float* gamma  = (const float*)d_in[3];
    const float* beta   = (const float*)d_in[4];
    const float* proj_w = (const float*)d_in[5];
    float* out = (float*)d_out;

    k_wstats<<<1, 512>>>(proj_w);
    k_wquant<<<512, 512>>>(proj_w);
    k_wsplit<<<(CC*CC*3)/256, 256>>>(conv_w);
    k_xsplit<<<dim3(LL/32, CC/64, BB), dim3(32, 8)>>>(x);
    k_convmma<<<dim3(NTOK/128, CC/128), 256>>>(conv_b);
    k_stats1<<<NSTATB, 256>>>();
    k_stats2<<<1, 512>>>();
    k_quant<<<NTOK, 128>>>(gamma, beta);
    k_mm<<<dim3(NTOK/64, CC/64), 256>>>(x, out);
}